// round 6
// baseline (speedup 1.0000x reference)
#include <cuda_runtime.h>
#include <cuda_bf16.h>

#define CRF_B 512
#define CRF_T 1024
#define CRF_K 64
#define WPB 4   // warps per block

typedef unsigned long long ull;

#define FMA2(acc, p, e) \
    asm("fma.rn.f32x2 %0, %1, %2, %3;" : "=l"(acc) : "l"(p), "l"(e), "l"(acc))
#define UNPK(lo, hi, v) \
    asm("mov.b64 {%0,%1}, %2;" : "=f"(lo), "=f"(hi) : "l"(v))
#define PK(v, lo, hi) \
    asm("mov.b64 %0, {%1,%2};" : "=l"(v) : "f"(lo), "f"(hi))

__device__ float g_per_batch[CRF_B];

__global__ void __launch_bounds__(32 * WPB, 1) crf_forward_kernel(
    const float* __restrict__ emissions,       // [B, T, K] f32
    const float* __restrict__ transitions,     // [K, K] f32
    const float* __restrict__ start_t,         // [K] f32
    const float* __restrict__ end_t,           // [K] f32
    const int* __restrict__ tags,              // [B, T] int32
    const int* __restrict__ mask)              // [B, T] int32
{
    __shared__ __align__(16) float pbuf[WPB][2][CRF_K];

    const int warp = threadIdx.x >> 5;
    const int lane = threadIdx.x & 31;
    const int b = blockIdx.x * WPB + warp;
    const unsigned FULL = 0xffffffffu;

    const float* em = emissions + (size_t)b * CRF_T * CRF_K;
    const int* tg = tags + (size_t)b * CRF_T;
    const int* mk = mask + (size_t)b * CRF_T;

    // ---------------- numerator (gold-path score) ----------------
    float part = 0.f;
    int cnt = 0;
    for (int t = lane; t < CRF_T; t += 32) {
        int m = (mk[t] != 0) ? 1 : 0;
        cnt += m;
        if (t > 0 && m) {
            int tag  = tg[t];
            int ptag = tg[t - 1];
            part += em[t * CRF_K + tag] + transitions[ptag * CRF_K + tag];
        }
    }
    #pragma unroll
    for (int off = 16; off; off >>= 1) {
        part += __shfl_xor_sync(FULL, part, off);
        cnt  += __shfl_xor_sync(FULL, cnt,  off);
    }
    float numer = 0.f;
    if (lane == 0) {
        int tag0 = tg[0];
        numer = part + em[tag0] + start_t[tag0];
        numer += end_t[tg[cnt - 1]];
    }

    // ------- E = exp(transitions), packed pairs over consecutive i -------
    // EA[k] = (E[2k][lane],    E[2k+1][lane])      -> output state j = lane
    // EB[k] = (E[2k][lane+32], E[2k+1][lane+32])   -> output state j = lane+32
    ull EA[CRF_K / 2];
    ull EB[CRF_K / 2];
    #pragma unroll
    for (int k = 0; k < CRF_K / 2; k++) {
        float a = __expf(transitions[(2 * k) * CRF_K + lane]);
        float c = __expf(transitions[(2 * k + 1) * CRF_K + lane]);
        PK(EA[k], a, c);
        float d = __expf(transitions[(2 * k) * CRF_K + lane + 32]);
        float e = __expf(transitions[(2 * k + 1) * CRF_K + lane + 32]);
        PK(EB[k], d, e);
    }

    // ---------------- init: p = exp(alpha0 - ref0), C = ref0 ----------------
    float a0 = em[lane]      + start_t[lane];
    float a1 = em[lane + 32] + start_t[lane + 32];
    float r0 = fmaxf(a0, a1);
    #pragma unroll
    for (int off = 16; off; off >>= 1)
        r0 = fmaxf(r0, __shfl_xor_sync(FULL, r0, off));
    float p0 = __expf(a0 - r0);
    float p1 = __expf(a1 - r0);
    float C = r0;

    // pipeline: w(t) = exp(e(t) - delta(t)), delta(t) = warp-max of e(t)
    float wc0, wc1, dc, wn0, wn1, dn;
    {
        float e10 = em[CRF_K + lane],     e11 = em[CRF_K + 32 + lane];
        float dm = fmaxf(e10, e11);
        #pragma unroll
        for (int off = 16; off; off >>= 1)
            dm = fmaxf(dm, __shfl_xor_sync(FULL, dm, off));
        dc = dm; wc0 = __expf(e10 - dm); wc1 = __expf(e11 - dm);

        float e20 = em[2 * CRF_K + lane], e21 = em[2 * CRF_K + 32 + lane];
        float dm2 = fmaxf(e20, e21);
        #pragma unroll
        for (int off = 16; off; off >>= 1)
            dm2 = fmaxf(dm2, __shfl_xor_sync(FULL, dm2, off));
        dn = dm2; wn0 = __expf(e20 - dm2); wn1 = __expf(e21 - dm2);
    }
    int mc = mk[1];
    int mn = mk[2];

    // seed p buffer for t = 1
    {
        float* pb0 = pbuf[warp][0];
        pb0[lane] = p0;
        pb0[lane + 32] = p1;
        __syncwarp();
    }

    for (int t = 1; t < CRF_T; ++t) {
        // prefetch t+2 and compute its (w, delta) in the shadow
        float ep0 = 0.f, ep1 = 0.f;
        int mp = 0;
        if (t + 2 < CRF_T) {
            ep0 = em[(t + 2) * CRF_K + lane];
            ep1 = em[(t + 2) * CRF_K + 32 + lane];
            mp  = mk[t + 2];
        }
        float dm = fmaxf(ep0, ep1);
        #pragma unroll
        for (int off = 16; off; off >>= 1)
            dm = fmaxf(dm, __shfl_xor_sync(FULL, dm, off));
        float dp = dm;
        float wp0 = __expf(ep0 - dm);
        float wp1 = __expf(ep1 - dm);

        // matvec: s_j = sum_i p_i * E[i][j]  (packed even/odd halves)
        const ulonglong2* pv = (const ulonglong2*)pbuf[warp][(t - 1) & 1];
        ull accA0 = 0ull, accA1 = 0ull, accB0 = 0ull, accB1 = 0ull;
        #pragma unroll
        for (int q = 0; q < 16; q++) {
            ulonglong2 u = pv[q];           // LDS.128 broadcast: p[4q..4q+3]
            FMA2(accA0, u.x, EA[2 * q]);
            FMA2(accA1, u.y, EA[2 * q + 1]);
            FMA2(accB0, u.x, EB[2 * q]);
            FMA2(accB1, u.y, EB[2 * q + 1]);
        }
        float sA, sB;
        {
            float x0, x1, y0, y1;
            UNPK(x0, x1, accA0); UNPK(y0, y1, accA1);
            sA = (x0 + x1) + (y0 + y1);
            UNPK(x0, x1, accB0); UNPK(y0, y1, accB1);
            sB = (x0 + x1) + (y0 + y1);
        }

        // exp-space update: p' = s * w, C += delta (masked)
        bool mm = (mc != 0);
        float np0 = sA * wc0;
        float np1 = sB * wc1;
        p0 = mm ? np0 : p0;
        p1 = mm ? np1 : p1;
        C  = mm ? C + dc : C;

        // periodic renormalization (keeps p in fp32 range)
        if ((t & 15) == 0) {
            float r = __shfl_sync(FULL, p0, 0);
            C += __logf(r);
            float inv = __fdividef(1.0f, r);
            p0 *= inv;
            p1 *= inv;
        }

        float* pb = pbuf[warp][t & 1];
        pb[lane] = p0;
        pb[lane + 32] = p1;
        __syncwarp();

        // rotate pipelines
        wc0 = wn0; wc1 = wn1; dc = dn;
        wn0 = wp0; wn1 = wp1; dn = dp;
        mc = mn; mn = mp;
    }

    // ---------------- final: denom = C + log(sum_j p_j * exp(end_j)) ----------------
    float s = p0 * __expf(end_t[lane]) + p1 * __expf(end_t[lane + 32]);
    #pragma unroll
    for (int off = 16; off; off >>= 1)
        s += __shfl_xor_sync(FULL, s, off);

    if (lane == 0) {
        float denom = C + __logf(s);
        g_per_batch[b] = denom - numer;
    }
}

__global__ void crf_reduce_kernel(float* __restrict__ out)
{
    __shared__ float sh[CRF_B];
    int t = threadIdx.x;
    sh[t] = g_per_batch[t];
    __syncthreads();
    #pragma unroll
    for (int s = CRF_B / 2; s > 0; s >>= 1) {
        if (t < s) sh[t] += sh[t + s];
        __syncthreads();
    }
    if (t == 0) out[0] = sh[0] * (1.0f / (float)CRF_B);
}

extern "C" void kernel_launch(void* const* d_in, const int* in_sizes, int n_in,
                              void* d_out, int out_size)
{
    const float* emissions   = (const float*)d_in[0];
    const float* transitions = (const float*)d_in[1];
    const float* start_t     = (const float*)d_in[2];
    const float* end_t       = (const float*)d_in[3];
    const int* tags          = (const int*)d_in[4];
    const int* mask          = (const int*)d_in[5];

    crf_forward_kernel<<<CRF_B / WPB, 32 * WPB>>>(emissions, transitions, start_t, end_t, tags, mask);
    crf_reduce_kernel<<<1, CRF_B>>>((float*)d_out);
}